// round 3
// baseline (speedup 1.0000x reference)
#include <cuda_runtime.h>
#include <cuda_bf16.h>
#include <cstdint>
#include <cstddef>

#define DEVINL __device__ __forceinline__

#define BB 8192
#define LL 2048
#define NFLOW 8

// GEMM tiling (mma.sync path — tcgen05 PTX is rejected by this build's compute_103 target)
#define BM 128
#define BN 128
#define BK 32
#define NKI (LL / BK)              // 64 k-chunks

// smem: rows padded to 80 bytes (32 bf16 = 64B data + 16B pad) -> conflict-free ldmatrix
#define ROWB 80
#define MAT_BYTES (128 * ROWB)     // 10240 per matrix tile
#define OFF_AH 0
#define OFF_AL (1 * MAT_BYTES)
#define OFF_BH (2 * MAT_BYTES)
#define OFF_BL (3 * MAT_BYTES)
#define STAGE_BYTES (4 * MAT_BYTES)        // 40960
#define SMEM_TOTAL (2 * STAGE_BYTES)       // 81920

// ---------------- scratch (__device__ globals; no allocation) ----------------
__device__ __nv_bfloat16 g_Vhi[(size_t)BB * LL];
__device__ __nv_bfloat16 g_Vlo[(size_t)BB * LL];
__device__ __nv_bfloat16 g_Whi[(size_t)NFLOW * LL * LL];
__device__ __nv_bfloat16 g_Wlo[(size_t)NFLOW * LL * LL];
__device__ float         g_V[(size_t)BB * LL];

// ---------------- PTX helpers (sm_80-level only) ----------------
DEVINL uint32_t smem_u32(const void* p) {
    uint32_t a;
    asm("{ .reg .u64 t; cvta.to.shared.u64 t, %1; cvt.u32.u64 %0, t; }" : "=r"(a) : "l"(p));
    return a;
}

DEVINL void cp_async16(uint32_t saddr, const void* gaddr) {
    asm volatile("cp.async.cg.shared.global [%0], [%1], 16;" :: "r"(saddr), "l"(gaddr) : "memory");
}
DEVINL void cp_commit() { asm volatile("cp.async.commit_group;" ::: "memory"); }
DEVINL void cp_wait_all() { asm volatile("cp.async.wait_group 0;" ::: "memory"); }

DEVINL void ldsm_x4(uint32_t& r0, uint32_t& r1, uint32_t& r2, uint32_t& r3, uint32_t saddr) {
    asm volatile("ldmatrix.sync.aligned.m8n8.x4.shared.b16 {%0,%1,%2,%3}, [%4];"
                 : "=r"(r0), "=r"(r1), "=r"(r2), "=r"(r3) : "r"(saddr));
}

DEVINL void mma_bf16(float* d, const uint32_t* a, const uint32_t* b) {
    asm volatile(
        "mma.sync.aligned.m16n8k16.row.col.f32.bf16.bf16.f32 "
        "{%0,%1,%2,%3}, {%4,%5,%6,%7}, {%8,%9}, {%0,%1,%2,%3};"
        : "+f"(d[0]), "+f"(d[1]), "+f"(d[2]), "+f"(d[3])
        : "r"(a[0]), "r"(a[1]), "r"(a[2]), "r"(a[3]), "r"(b[0]), "r"(b[1]));
}

DEVINL uint32_t pack_bf2(float a, float b) {
    __nv_bfloat162 t; t.x = __float2bfloat16(a); t.y = __float2bfloat16(b);
    return *reinterpret_cast<uint32_t*>(&t);
}

// ---------------- split: fp32 -> bf16 hi/lo ----------------
__global__ void __launch_bounds__(256) split_kernel(
    const float4* __restrict__ src, uint2* __restrict__ hi, uint2* __restrict__ lo, int n4)
{
    int i = blockIdx.x * 256 + threadIdx.x;
    if (i >= n4) return;
    float4 v = src[i];
    float hx = __bfloat162float(__float2bfloat16(v.x));
    float hy = __bfloat162float(__float2bfloat16(v.y));
    float hz = __bfloat162float(__float2bfloat16(v.z));
    float hw = __bfloat162float(__float2bfloat16(v.w));
    uint2 h, l;
    h.x = pack_bf2(hx, hy);          h.y = pack_bf2(hz, hw);
    l.x = pack_bf2(v.x - hx, v.y - hy);
    l.y = pack_bf2(v.z - hz, v.w - hw);
    hi[i] = h; lo[i] = l;
}

// ---------------- GEMM: out[M,N] = A[M,K] @ W[N,K]^T + bias ----------------
// bf16 3-product split: D = Ah*Bh + Ah*Bl + Al*Bh  (fp32 accumulate)
__global__ void __launch_bounds__(256) gemm_kernel(
    const __nv_bfloat16* __restrict__ Ahi, const __nv_bfloat16* __restrict__ Alo,
    const __nv_bfloat16* __restrict__ Bhi, const __nv_bfloat16* __restrict__ Blo,
    const float* __restrict__ bias, float* __restrict__ out)
{
    extern __shared__ char smem[];
    const uint32_t sb = smem_u32(smem);
    const int tid = threadIdx.x;
    const int lane = tid & 31;
    const int wid = tid >> 5;
    const int warp_m = wid & 3;          // 4 warps along M (32 rows each)
    const int warp_n = wid >> 2;         // 2 warps along N (64 cols each)
    const size_t arow0 = (size_t)blockIdx.x * BM;
    const size_t brow0 = (size_t)blockIdx.y * BN;

    float acc[2][8][4];
    #pragma unroll
    for (int mi = 0; mi < 2; ++mi)
        #pragma unroll
        for (int ni = 0; ni < 8; ++ni)
            #pragma unroll
            for (int q = 0; q < 4; ++q) acc[mi][ni][q] = 0.0f;

    // per-thread cp.async coords: each thread copies 2 chunks/matrix
    // chunk id i in [0,512): row = i>>2, c16 = i&3
    // ldmatrix source addresses (within a matrix tile, byte offsets):
    //   A (x4): row = warp_m*32 + s*16 + (lane&15); kbyte = ks*32 + (lane>>4)*16
    //   B (x4): row = warp_n*64 + p*16 + ((lane>>4)&1)*8 + (lane&7); kbyte = ks*32 + ((lane>>3)&1)*16
    const uint32_t a_row[2] = {
        (uint32_t)(warp_m * 32 + 0  + (lane & 15)),
        (uint32_t)(warp_m * 32 + 16 + (lane & 15)) };
    const uint32_t a_kb = (uint32_t)((lane >> 4) * 16);
    const uint32_t b_row_base = (uint32_t)(warp_n * 64 + ((lane >> 4) & 1) * 8 + (lane & 7));
    const uint32_t b_kb = (uint32_t)(((lane >> 3) & 1) * 16);

    // ---- prefetch stage 0 ----
    {
        const uint32_t stg = sb;                    // stage 0
        #pragma unroll
        for (int it = 0; it < 2; ++it) {
            int i = tid + it * 256;                 // 0..511
            int r = i >> 2, c = i & 3;
            uint32_t so = (uint32_t)(r * ROWB + c * 16);
            size_t ga = (arow0 + r) * (size_t)LL + c * 8;
            size_t gb = (brow0 + r) * (size_t)LL + c * 8;
            cp_async16(stg + OFF_AH + so, Ahi + ga);
            cp_async16(stg + OFF_AL + so, Alo + ga);
            cp_async16(stg + OFF_BH + so, Bhi + gb);
            cp_async16(stg + OFF_BL + so, Blo + gb);
        }
        cp_commit();
    }

    for (int kc = 0; kc < NKI; ++kc) {
        cp_wait_all();
        __syncthreads();

        // prefetch next chunk into the other stage (overlaps with compute below)
        if (kc + 1 < NKI) {
            const uint32_t stg = sb + ((kc + 1) & 1) * STAGE_BYTES;
            const size_t kb = (size_t)(kc + 1) * BK;
            #pragma unroll
            for (int it = 0; it < 2; ++it) {
                int i = tid + it * 256;
                int r = i >> 2, c = i & 3;
                uint32_t so = (uint32_t)(r * ROWB + c * 16);
                size_t ga = (arow0 + r) * (size_t)LL + kb + c * 8;
                size_t gb = (brow0 + r) * (size_t)LL + kb + c * 8;
                cp_async16(stg + OFF_AH + so, Ahi + ga);
                cp_async16(stg + OFF_AL + so, Alo + ga);
                cp_async16(stg + OFF_BH + so, Bhi + gb);
                cp_async16(stg + OFF_BL + so, Blo + gb);
            }
            cp_commit();
        }

        const uint32_t stg = sb + (kc & 1) * STAGE_BYTES;

        #pragma unroll
        for (int ks = 0; ks < 2; ++ks) {          // two k16 steps per BK=32
            uint32_t Ah[2][4], Al[2][4];
            #pragma unroll
            for (int s = 0; s < 2; ++s) {
                uint32_t off = a_row[s] * ROWB + ks * 32 + a_kb;
                ldsm_x4(Ah[s][0], Ah[s][1], Ah[s][2], Ah[s][3], stg + OFF_AH + off);
                ldsm_x4(Al[s][0], Al[s][1], Al[s][2], Al[s][3], stg + OFF_AL + off);
            }
            uint32_t Bh[8][2], Bl[8][2];
            #pragma unroll
            for (int p = 0; p < 4; ++p) {         // each x4 covers 2 n-subtiles
                uint32_t off = (b_row_base + p * 16) * ROWB + ks * 32 + b_kb;
                ldsm_x4(Bh[2*p][0], Bh[2*p][1], Bh[2*p+1][0], Bh[2*p+1][1], stg + OFF_BH + off);
                ldsm_x4(Bl[2*p][0], Bl[2*p][1], Bl[2*p+1][0], Bl[2*p+1][1], stg + OFF_BL + off);
            }
            #pragma unroll
            for (int mi = 0; mi < 2; ++mi)
                #pragma unroll
                for (int ni = 0; ni < 8; ++ni) {
                    mma_bf16(acc[mi][ni], Ah[mi], Bh[ni]);
                    mma_bf16(acc[mi][ni], Ah[mi], Bl[ni]);
                    mma_bf16(acc[mi][ni], Al[mi], Bh[ni]);
                }
        }
        __syncthreads();
    }

    // ---- epilogue: D-frag layout: thread t: (m = t/4 [+8], n = 2*(t%4) [+1]) ----
    const size_t m_base = arow0 + warp_m * 32;
    const size_t n_base = brow0 + warp_n * 64;
    const int tm = lane >> 2, tn = (lane & 3) * 2;
    #pragma unroll
    for (int mi = 0; mi < 2; ++mi) {
        #pragma unroll
        for (int ni = 0; ni < 8; ++ni) {
            size_t col = n_base + ni * 8 + tn;
            float b0 = __ldg(bias + col), b1 = __ldg(bias + col + 1);
            size_t r0 = m_base + mi * 16 + tm;
            float2 v0 = { acc[mi][ni][0] + b0, acc[mi][ni][1] + b1 };
            float2 v1 = { acc[mi][ni][2] + b0, acc[mi][ni][3] + b1 };
            *(float2*)(out + r0 * LL + col)        = v0;
            *(float2*)(out + (r0 + 8) * LL + col)  = v1;
        }
    }
}

// ---------------- Householder: z' = z - 2 v (v.z)/(v.v); also split v ----------------
__global__ void __launch_bounds__(256) hflow_kernel(
    const float* __restrict__ v, const float* __restrict__ zin, float* __restrict__ zout,
    uint2* __restrict__ vhi, uint2* __restrict__ vlo)
{
    __shared__ float red[16];
    __shared__ float s_coef;
    const size_t row = blockIdx.x;
    const int tid = threadIdx.x;
    const float4* v4 = (const float4*)(v + row * (size_t)LL);
    const float4* z4 = (const float4*)(zin + row * (size_t)LL);
    float4 va = v4[tid], vb = v4[tid + 256];
    float4 za = z4[tid], zb = z4[tid + 256];

    float vz = va.x*za.x + va.y*za.y + va.z*za.z + va.w*za.w
             + vb.x*zb.x + vb.y*zb.y + vb.z*zb.z + vb.w*zb.w;
    float vv = va.x*va.x + va.y*va.y + va.z*va.z + va.w*va.w
             + vb.x*vb.x + vb.y*vb.y + vb.z*vb.z + vb.w*vb.w;
    #pragma unroll
    for (int o = 16; o; o >>= 1) {
        vz += __shfl_xor_sync(0xFFFFFFFFu, vz, o);
        vv += __shfl_xor_sync(0xFFFFFFFFu, vv, o);
    }
    if ((tid & 31) == 0) { red[tid >> 5] = vz; red[8 + (tid >> 5)] = vv; }
    __syncthreads();
    if (tid == 0) {
        float svz = 0.f, svv = 0.f;
        #pragma unroll
        for (int i = 0; i < 8; ++i) { svz += red[i]; svv += red[8 + i]; }
        s_coef = -2.0f * svz / svv;
    }
    __syncthreads();
    const float c = s_coef;

    float4 oa, ob;
    oa.x = za.x + c*va.x; oa.y = za.y + c*va.y; oa.z = za.z + c*va.z; oa.w = za.w + c*va.w;
    ob.x = zb.x + c*vb.x; ob.y = zb.y + c*vb.y; ob.z = zb.z + c*vb.z; ob.w = zb.w + c*vb.w;
    float4* zo = (float4*)(zout + row * (size_t)LL);
    zo[tid] = oa; zo[tid + 256] = ob;

    // split v for the next GEMM
    size_t base = row * (size_t)(LL / 4);
    #pragma unroll
    for (int h = 0; h < 2; ++h) {
        float4 vv4 = h ? vb : va;
        float hx = __bfloat162float(__float2bfloat16(vv4.x));
        float hy = __bfloat162float(__float2bfloat16(vv4.y));
        float hz = __bfloat162float(__float2bfloat16(vv4.z));
        float hw = __bfloat162float(__float2bfloat16(vv4.w));
        uint2 hv, lv;
        hv.x = pack_bf2(hx, hy);               hv.y = pack_bf2(hz, hw);
        lv.x = pack_bf2(vv4.x - hx, vv4.y - hy);
        lv.y = pack_bf2(vv4.z - hz, vv4.w - hw);
        size_t idx = base + tid + h * 256;
        vhi[idx] = hv; vlo[idx] = lv;
    }
}

// ---------------- host ----------------
extern "C" void kernel_launch(void* const* d_in, const int* in_sizes, int n_in,
                              void* d_out, int out_size)
{
    const float* z_in   = (const float*)d_in[0];
    const float* h_last = (const float*)d_in[1];
    const float* W0     = (const float*)d_in[2];
    const float* b0     = (const float*)d_in[3];
    const float* Ws     = (const float*)d_in[4];
    const float* bs     = (const float*)d_in[5];
    float* z_out = (float*)d_out;

    void *pVhi, *pVlo, *pWhi, *pWlo, *pV;
    cudaGetSymbolAddress(&pVhi, g_Vhi);
    cudaGetSymbolAddress(&pVlo, g_Vlo);
    cudaGetSymbolAddress(&pWhi, g_Whi);
    cudaGetSymbolAddress(&pWlo, g_Wlo);
    cudaGetSymbolAddress(&pV,   g_V);

    static bool attr_set = false;
    if (!attr_set) {
        cudaFuncSetAttribute(gemm_kernel, cudaFuncAttributeMaxDynamicSharedMemorySize, SMEM_TOTAL);
        attr_set = true;
    }

    const size_t mat = (size_t)LL * LL;
    // split h_last -> V hi/lo
    {
        int n4 = (int)((size_t)BB * LL / 4);
        split_kernel<<<(n4 + 255) / 256, 256>>>((const float4*)h_last, (uint2*)pVhi, (uint2*)pVlo, n4);
    }
    // split W0 -> slot 0
    {
        int n4 = (int)(mat / 4);
        split_kernel<<<(n4 + 255) / 256, 256>>>((const float4*)W0, (uint2*)pWhi, (uint2*)pWlo, n4);
    }
    // split Ws -> slots 1..7
    {
        int n4 = (int)((NFLOW - 1) * mat / 4);
        split_kernel<<<(n4 + 255) / 256, 256>>>((const float4*)Ws,
            (uint2*)((__nv_bfloat16*)pWhi + mat), (uint2*)((__nv_bfloat16*)pWlo + mat), n4);
    }

    dim3 ggrid(BB / BM, LL / BN);   // (64, 16)
    for (int j = 0; j < NFLOW; ++j) {
        const __nv_bfloat16* Bh = (const __nv_bfloat16*)pWhi + (size_t)j * mat;
        const __nv_bfloat16* Bl = (const __nv_bfloat16*)pWlo + (size_t)j * mat;
        const float* bias = (j == 0) ? b0 : (bs + (size_t)(j - 1) * LL);
        gemm_kernel<<<ggrid, 256, SMEM_TOTAL>>>(
            (const __nv_bfloat16*)pVhi, (const __nv_bfloat16*)pVlo, Bh, Bl, bias, (float*)pV);
        const float* zi = (j == 0) ? z_in : z_out;
        hflow_kernel<<<BB, 256>>>((const float*)pV, zi, z_out, (uint2*)pVhi, (uint2*)pVlo);
    }
}

// round 6
// speedup vs baseline: 1.0099x; 1.0099x over previous
#include <cuda_runtime.h>
#include <cuda_bf16.h>
#include <cstdint>
#include <cstddef>

#define DEVINL __device__ __forceinline__

#define BB 8192
#define LL 2048
#define NFLOW 8

// GEMM tiling (mma.sync path — tcgen05 PTX rejected by this build's compute_103 target)
#define BM 128
#define BN 128
#define BK 32
#define NKI (LL / BK)              // 64 k-chunks

// smem rows padded to 80B (64B data + 16B pad) -> conflict-free ldmatrix
#define ROWB 80
#define MAT_BYTES (128 * ROWB)
#define OFF_AH 0
#define OFF_AL (1 * MAT_BYTES)
#define OFF_BH (2 * MAT_BYTES)
#define OFF_BL (3 * MAT_BYTES)
#define STAGE_BYTES (4 * MAT_BYTES)        // 40960
#define SMEM_TOTAL (2 * STAGE_BYTES)       // 81920

// ---------------- scratch ----------------
__device__ __nv_bfloat16 g_VhiA[(size_t)BB * LL];
__device__ __nv_bfloat16 g_VloA[(size_t)BB * LL];
__device__ __nv_bfloat16 g_VhiB[(size_t)BB * LL];
__device__ __nv_bfloat16 g_VloB[(size_t)BB * LL];
__device__ __nv_bfloat16 g_Whi[(size_t)NFLOW * LL * LL];
__device__ __nv_bfloat16 g_Wlo[(size_t)NFLOW * LL * LL];

// ---------------- PTX helpers ----------------
DEVINL uint32_t smem_u32(const void* p) {
    uint32_t a;
    asm("{ .reg .u64 t; cvta.to.shared.u64 t, %1; cvt.u32.u64 %0, t; }" : "=r"(a) : "l"(p));
    return a;
}
DEVINL void cp_async16(uint32_t saddr, const void* gaddr) {
    asm volatile("cp.async.cg.shared.global [%0], [%1], 16;" :: "r"(saddr), "l"(gaddr) : "memory");
}
DEVINL void cp_commit() { asm volatile("cp.async.commit_group;" ::: "memory"); }
DEVINL void cp_wait_all() { asm volatile("cp.async.wait_group 0;" ::: "memory"); }

DEVINL void ldsm_x4(uint32_t& r0, uint32_t& r1, uint32_t& r2, uint32_t& r3, uint32_t saddr) {
    asm volatile("ldmatrix.sync.aligned.m8n8.x4.shared.b16 {%0,%1,%2,%3}, [%4];"
                 : "=r"(r0), "=r"(r1), "=r"(r2), "=r"(r3) : "r"(saddr));
}
DEVINL void mma_bf16(float* d, const uint32_t* a, const uint32_t* b) {
    asm volatile(
        "mma.sync.aligned.m16n8k16.row.col.f32.bf16.bf16.f32 "
        "{%0,%1,%2,%3}, {%4,%5,%6,%7}, {%8,%9}, {%0,%1,%2,%3};"
        : "+f"(d[0]), "+f"(d[1]), "+f"(d[2]), "+f"(d[3])
        : "r"(a[0]), "r"(a[1]), "r"(a[2]), "r"(a[3]), "r"(b[0]), "r"(b[1]));
}
DEVINL uint32_t pack_bf2(float a, float b) {
    __nv_bfloat162 t; t.x = __float2bfloat16(a); t.y = __float2bfloat16(b);
    return *reinterpret_cast<uint32_t*>(&t);
}
// split two fp32 into packed bf16 hi pair + lo pair
DEVINL void split2(float a, float b, uint32_t& hi, uint32_t& lo) {
    float ha = __bfloat162float(__float2bfloat16(a));
    float hb = __bfloat162float(__float2bfloat16(b));
    hi = pack_bf2(ha, hb);
    lo = pack_bf2(a - ha, b - hb);
}

// ---------------- split: fp32 -> bf16 hi/lo ----------------
__global__ void __launch_bounds__(256) split_kernel(
    const float4* __restrict__ src, uint2* __restrict__ hi, uint2* __restrict__ lo, int n4)
{
    int i = blockIdx.x * 256 + threadIdx.x;
    if (i >= n4) return;
    float4 v = src[i];
    uint2 h, l;
    split2(v.x, v.y, h.x, l.x);
    split2(v.z, v.w, h.y, l.y);
    hi[i] = h; lo[i] = l;
}

// ---------------- GEMM: v' = A @ W^T + bias, epilogue-split into vhi/vlo ----------------
// bf16 3-product: D = Ah*Bh + Al*Bh + Ah*Bl   (fp32 accumulate)
__global__ void __launch_bounds__(256, 2) gemm_kernel(
    const __nv_bfloat16* __restrict__ Ahi, const __nv_bfloat16* __restrict__ Alo,
    const __nv_bfloat16* __restrict__ Bhi, const __nv_bfloat16* __restrict__ Blo,
    const float* __restrict__ bias,
    __nv_bfloat16* __restrict__ vhi_out, __nv_bfloat16* __restrict__ vlo_out)
{
    extern __shared__ char smem[];
    const uint32_t sb = smem_u32(smem);
    const int tid = threadIdx.x;
    const int lane = tid & 31;
    const int wid = tid >> 5;
    const int warp_m = wid & 3;          // 4 warps along M (32 rows)
    const int warp_n = wid >> 2;         // 2 warps along N (64 cols)
    const size_t arow0 = (size_t)blockIdx.x * BM;
    const size_t brow0 = (size_t)blockIdx.y * BN;

    float acc[2][8][4];
    #pragma unroll
    for (int mi = 0; mi < 2; ++mi)
        #pragma unroll
        for (int ni = 0; ni < 8; ++ni)
            #pragma unroll
            for (int q = 0; q < 4; ++q) acc[mi][ni][q] = 0.0f;

    const uint32_t a_row[2] = {
        (uint32_t)(warp_m * 32 + 0  + (lane & 15)),
        (uint32_t)(warp_m * 32 + 16 + (lane & 15)) };
    const uint32_t a_kb = (uint32_t)((lane >> 4) * 16);
    const uint32_t b_row_base = (uint32_t)(warp_n * 64 + ((lane >> 4) & 1) * 8 + (lane & 7));
    const uint32_t b_kb = (uint32_t)(((lane >> 3) & 1) * 16);

    // ---- prefetch stage 0 ----
    {
        const uint32_t stg = sb;
        #pragma unroll
        for (int it = 0; it < 2; ++it) {
            int i = tid + it * 256;
            int r = i >> 2, c = i & 3;
            uint32_t so = (uint32_t)(r * ROWB + c * 16);
            size_t ga = (arow0 + r) * (size_t)LL + c * 8;
            size_t gb = (brow0 + r) * (size_t)LL + c * 8;
            cp_async16(stg + OFF_AH + so, Ahi + ga);
            cp_async16(stg + OFF_AL + so, Alo + ga);
            cp_async16(stg + OFF_BH + so, Bhi + gb);
            cp_async16(stg + OFF_BL + so, Blo + gb);
        }
        cp_commit();
    }

    for (int kc = 0; kc < NKI; ++kc) {
        cp_wait_all();
        __syncthreads();   // single barrier: fill visible AND prior reads of other buf done

        if (kc + 1 < NKI) {
            const uint32_t stg = sb + ((kc + 1) & 1) * STAGE_BYTES;
            const size_t kb = (size_t)(kc + 1) * BK;
            #pragma unroll
            for (int it = 0; it < 2; ++it) {
                int i = tid + it * 256;
                int r = i >> 2, c = i & 3;
                uint32_t so = (uint32_t)(r * ROWB + c * 16);
                size_t ga = (arow0 + r) * (size_t)LL + kb + c * 8;
                size_t gb = (brow0 + r) * (size_t)LL + kb + c * 8;
                cp_async16(stg + OFF_AH + so, Ahi + ga);
                cp_async16(stg + OFF_AL + so, Alo + ga);
                cp_async16(stg + OFF_BH + so, Bhi + gb);
                cp_async16(stg + OFF_BL + so, Blo + gb);
            }
            cp_commit();
        }

        const uint32_t stg = sb + (kc & 1) * STAGE_BYTES;

        #pragma unroll
        for (int ks = 0; ks < 2; ++ks) {
            // pass 1: Ah * Bh
            uint32_t Ah[2][4];
            #pragma unroll
            for (int s = 0; s < 2; ++s) {
                uint32_t off = a_row[s] * ROWB + ks * 32 + a_kb;
                ldsm_x4(Ah[s][0], Ah[s][1], Ah[s][2], Ah[s][3], stg + OFF_AH + off);
            }
            uint32_t Bh[8][2];
            #pragma unroll
            for (int p = 0; p < 4; ++p) {
                uint32_t off = (b_row_base + p * 16) * ROWB + ks * 32 + b_kb;
                ldsm_x4(Bh[2*p][0], Bh[2*p][1], Bh[2*p+1][0], Bh[2*p+1][1], stg + OFF_BH + off);
            }
            #pragma unroll
            for (int mi = 0; mi < 2; ++mi)
                #pragma unroll
                for (int ni = 0; ni < 8; ++ni)
                    mma_bf16(acc[mi][ni], Ah[mi], Bh[ni]);

            // pass 2: Al * Bh  (Bh still live, Al replaces nothing yet)
            uint32_t Al[2][4];
            #pragma unroll
            for (int s = 0; s < 2; ++s) {
                uint32_t off = a_row[s] * ROWB + ks * 32 + a_kb;
                ldsm_x4(Al[s][0], Al[s][1], Al[s][2], Al[s][3], stg + OFF_AL + off);
            }
            #pragma unroll
            for (int mi = 0; mi < 2; ++mi)
                #pragma unroll
                for (int ni = 0; ni < 8; ++ni)
                    mma_bf16(acc[mi][ni], Al[mi], Bh[ni]);

            // pass 3: Ah * Bl  (Bh dead -> Bl can reuse its registers)
            uint32_t Bl[8][2];
            #pragma unroll
            for (int p = 0; p < 4; ++p) {
                uint32_t off = (b_row_base + p * 16) * ROWB + ks * 32 + b_kb;
                ldsm_x4(Bl[2*p][0], Bl[2*p][1], Bl[2*p+1][0], Bl[2*p+1][1], stg + OFF_BL + off);
            }
            #pragma unroll
            for (int mi = 0; mi < 2; ++mi)
                #pragma unroll
                for (int ni = 0; ni < 8; ++ni)
                    mma_bf16(acc[mi][ni], Ah[mi], Bl[ni]);
        }
        // no trailing __syncthreads: next iteration's top barrier protects reuse
    }

    // ---- epilogue: add bias, split fp32 -> bf16 hi/lo, store ----
    const size_t m_base = arow0 + warp_m * 32;
    const size_t n_base = brow0 + warp_n * 64;
    const int tm = lane >> 2, tn = (lane & 3) * 2;
    #pragma unroll
    for (int mi = 0; mi < 2; ++mi) {
        #pragma unroll
        for (int ni = 0; ni < 8; ++ni) {
            size_t col = n_base + ni * 8 + tn;
            float b0 = __ldg(bias + col), b1 = __ldg(bias + col + 1);
            size_t r0 = m_base + mi * 16 + tm;
            float v00 = acc[mi][ni][0] + b0, v01 = acc[mi][ni][1] + b1;
            float v10 = acc[mi][ni][2] + b0, v11 = acc[mi][ni][3] + b1;
            uint32_t h, l;
            split2(v00, v01, h, l);
            *(uint32_t*)(vhi_out + r0 * LL + col) = h;
            *(uint32_t*)(vlo_out + r0 * LL + col) = l;
            split2(v10, v11, h, l);
            *(uint32_t*)(vhi_out + (r0 + 8) * LL + col) = h;
            *(uint32_t*)(vlo_out + (r0 + 8) * LL + col) = l;
        }
    }
}

// ---------------- Householder: z' = z - 2 v (v.z)/(v.v), v = hi+lo ----------------
__global__ void __launch_bounds__(256) hflow_kernel(
    const __nv_bfloat16* __restrict__ vhi, const __nv_bfloat16* __restrict__ vlo,
    const float* __restrict__ zin, float* __restrict__ zout)
{
    __shared__ float red[16];
    __shared__ float s_coef;
    const size_t row = blockIdx.x;
    const int tid = threadIdx.x;
    const uint2* vh4 = (const uint2*)(vhi + row * (size_t)LL);   // 4 bf16 / uint2
    const uint2* vl4 = (const uint2*)(vlo + row * (size_t)LL);
    const float4* z4 = (const float4*)(zin + row * (size_t)LL);

    float v[8], z[8];
    #pragma unroll
    for (int h = 0; h < 2; ++h) {
        uint2 hv = vh4[tid + h * 256];
        uint2 lv = vl4[tid + h * 256];
        float4 zz = z4[tid + h * 256];
        __nv_bfloat162 h0 = *(__nv_bfloat162*)&hv.x, h1 = *(__nv_bfloat162*)&hv.y;
        __nv_bfloat162 l0 = *(__nv_bfloat162*)&lv.x, l1 = *(__nv_bfloat162*)&lv.y;
        v[h*4+0] = __bfloat162float(h0.x) + __bfloat162float(l0.x);
        v[h*4+1] = __bfloat162float(h0.y) + __bfloat162float(l0.y);
        v[h*4+2] = __bfloat162float(h1.x) + __bfloat162float(l1.x);
        v[h*4+3] = __bfloat162float(h1.y) + __bfloat162float(l1.y);
        z[h*4+0] = zz.x; z[h*4+1] = zz.y; z[h*4+2] = zz.z; z[h*4+3] = zz.w;
    }

    float vz = 0.f, vv = 0.f;
    #pragma unroll
    for (int i = 0; i < 8; ++i) { vz += v[i] * z[i]; vv += v[i] * v[i]; }
    #pragma unroll
    for (int o = 16; o; o >>= 1) {
        vz += __shfl_xor_sync(0xFFFFFFFFu, vz, o);
        vv += __shfl_xor_sync(0xFFFFFFFFu, vv, o);
    }
    if ((tid & 31) == 0) { red[tid >> 5] = vz; red[8 + (tid >> 5)] = vv; }
    __syncthreads();
    if (tid == 0) {
        float svz = 0.f, svv = 0.f;
        #pragma unroll
        for (int i = 0; i < 8; ++i) { svz += red[i]; svv += red[8 + i]; }
        s_coef = -2.0f * svz / svv;
    }
    __syncthreads();
    const float c = s_coef;

    float4* zo = (float4*)(zout + row * (size_t)LL);
    #pragma unroll
    for (int h = 0; h < 2; ++h) {
        float4 o;
        o.x = z[h*4+0] + c * v[h*4+0];
        o.y = z[h*4+1] + c * v[h*4+1];
        o.z = z[h*4+2] + c * v[h*4+2];
        o.w = z[h*4+3] + c * v[h*4+3];
        zo[tid + h * 256] = o;
    }
}

// ---------------- host ----------------
extern "C" void kernel_launch(void* const* d_in, const int* in_sizes, int n_in,
                              void* d_out, int out_size)
{
    const float* z_in   = (const float*)d_in[0];
    const float* h_last = (const float*)d_in[1];
    const float* W0     = (const float*)d_in[2];
    const float* b0     = (const float*)d_in[3];
    const float* Ws     = (const float*)d_in[4];
    const float* bs     = (const float*)d_in[5];
    float* z_out = (float*)d_out;

    void *pVhiA, *pVloA, *pVhiB, *pVloB, *pWhi, *pWlo;
    cudaGetSymbolAddress(&pVhiA, g_VhiA);
    cudaGetSymbolAddress(&pVloA, g_VloA);
    cudaGetSymbolAddress(&pVhiB, g_VhiB);
    cudaGetSymbolAddress(&pVloB, g_VloB);
    cudaGetSymbolAddress(&pWhi,  g_Whi);
    cudaGetSymbolAddress(&pWlo,  g_Wlo);

    static bool attr_set = false;
    if (!attr_set) {
        cudaFuncSetAttribute(gemm_kernel, cudaFuncAttributeMaxDynamicSharedMemorySize, SMEM_TOTAL);
        attr_set = true;
    }

    const size_t mat = (size_t)LL * LL;
    {   // split h_last -> A buffers
        int n4 = (int)((size_t)BB * LL / 4);
        split_kernel<<<(n4 + 255) / 256, 256>>>((const float4*)h_last, (uint2*)pVhiA, (uint2*)pVloA, n4);
    }
    {   // split W0 -> slot 0
        int n4 = (int)(mat / 4);
        split_kernel<<<(n4 + 255) / 256, 256>>>((const float4*)W0, (uint2*)pWhi, (uint2*)pWlo, n4);
    }
    {   // split Ws -> slots 1..7
        int n4 = (int)((NFLOW - 1) * mat / 4);
        split_kernel<<<(n4 + 255) / 256, 256>>>((const float4*)Ws,
            (uint2*)((__nv_bfloat16*)pWhi + mat), (uint2*)((__nv_bfloat16*)pWlo + mat), n4);
    }

    dim3 ggrid(BB / BM, LL / BN);   // (64, 16)
    void* curHi = pVhiA; void* curLo = pVloA;
    void* nxtHi = pVhiB; void* nxtLo = pVloB;
    for (int j = 0; j < NFLOW; ++j) {
        const __nv_bfloat16* Bh = (const __nv_bfloat16*)pWhi + (size_t)j * mat;
        const __nv_bfloat16* Bl = (const __nv_bfloat16*)pWlo + (size_t)j * mat;
        const float* bias = (j == 0) ? b0 : (bs + (size_t)(j - 1) * LL);
        gemm_kernel<<<ggrid, 256, SMEM_TOTAL>>>(
            (const __nv_bfloat16*)curHi, (const __nv_bfloat16*)curLo, Bh, Bl, bias,
            (__nv_bfloat16*)nxtHi, (__nv_bfloat16*)nxtLo);
        const float* zi = (j == 0) ? z_in : z_out;
        hflow_kernel<<<BB, 256>>>((const __nv_bfloat16*)nxtHi, (const __nv_bfloat16*)nxtLo, zi, z_out);
        void* t;
        t = curHi; curHi = nxtHi; nxtHi = t;
        t = curLo; curLo = nxtLo; nxtLo = t;
    }
}